// round 17
// baseline (speedup 1.0000x reference)
#include <cuda_runtime.h>
#include <cuda_bf16.h>
#include <math.h>

// ---------------- problem constants ----------------
#define KK 50
#define TT 50
#define VV 3000
#define LL 300
#define TH 800
#define EH 200
#define DD 256
#define SS 8

// ---------------- device scratch (static, no allocs) ----------------
__device__ double   g_acc[4];                 // nll, kl_alpha, kl_eta, kl_theta
__device__ float  g_x[TT * EH];
__device__ float  g_xw0[TT * 4 * EH];
__device__ float  g_xw1[TT * 4 * EH];
__device__ float  g_hs0[TT * EH];
__device__ float  g_hs1[TT * EH];
__device__ float  g_etas[TT * KK];
__device__ float  g_Amu[TT * KK];
__device__ float  g_Als[TT * KK];
__device__ float  g_eta_td[DD * KK];
__device__ float  g_h1[DD * TH];
__device__ float  g_h2[DD * TH];
__device__ float  g_theta[DD * KK];
__device__ float  g_wa[DD * KK * LL];
__device__ float  g_WmueT[KK * (EH + KK)];
__device__ float  g_WlseT[KK * (EH + KK)];
__device__ float  g_WmuthT[KK * TH];
__device__ float  g_WlsthT[KK * TH];
__device__ __nv_bfloat16 g_E[DD * KK * VV];   // exp(logit), bf16, 76.8 MB
__device__ float  g_Z[DD * KK];

// ---------------- helpers ----------------
__device__ __forceinline__ float sigm(float x) { return 1.0f / (1.0f + expf(-x)); }

__device__ __forceinline__ unsigned f2tf32(float f) {
    unsigned r;
    asm("cvt.rna.tf32.f32 %0, %1;" : "=r"(r) : "f"(f));
    return r;
}
__device__ __forceinline__ void mma_tf32(float* c, const unsigned* a, const unsigned* b) {
    asm volatile(
        "mma.sync.aligned.m16n8k8.row.col.f32.tf32.tf32.f32 "
        "{%0,%1,%2,%3}, {%4,%5,%6,%7}, {%8,%9}, {%0,%1,%2,%3};"
        : "+f"(c[0]), "+f"(c[1]), "+f"(c[2]), "+f"(c[3])
        : "r"(a[0]), "r"(a[1]), "r"(a[2]), "r"(a[3]), "r"(b[0]), "r"(b[1]));
}
__device__ __forceinline__ unsigned smem_u32(const void* p) {
    unsigned a;
    asm("{ .reg .u64 t; cvta.to.shared.u64 t, %1; cvt.u32.u64 %0, t; }"
        : "=r"(a) : "l"(p));
    return a;
}
__device__ __forceinline__ void dsmem_st(unsigned local_addr, int rank, float v) {
    asm volatile(
        "{ .reg .b32 r; mapa.shared::cluster.u32 r, %0, %1; "
        "st.shared::cluster.f32 [r], %2; }"
        :: "r"(local_addr), "r"(rank), "f"(v) : "memory");
}

__device__ __forceinline__ float block_reduce_256(float v, float* sr) {
    int tid = threadIdx.x;
#pragma unroll
    for (int off = 16; off; off >>= 1) v += __shfl_down_sync(0xffffffffu, v, off);
    if ((tid & 31) == 0) sr[tid >> 5] = v;
    __syncthreads();
    if (tid < 8) {
        v = sr[tid];
#pragma unroll
        for (int off = 4; off; off >>= 1) v += __shfl_down_sync(0xffu, v, off);
    }
    return v;
}

// ---------------- init ----------------
__global__ void k_warm() {}

__global__ void k_zero() {
    int idx = blockIdx.x * 256 + threadIdx.x;
    if (idx < DD * KK) g_Z[idx] = 0.0f;
    if (idx < 4) g_acc[idx] = 0.0;
}

// all bias fills in one launch: x, xw0, xw1, h2
__global__ void k_fill_all(const float* __restrict__ b_em, const float* __restrict__ bl0,
                           const float* __restrict__ bl1, const float* __restrict__ b_t2) {
    int idx = blockIdx.x * 256 + threadIdx.x;
    if (idx < TT * EH) { g_x[idx] = b_em[idx % EH]; return; }
    idx -= TT * EH;
    if (idx < TT * 4 * EH) { g_xw0[idx] = bl0[idx % (4 * EH)]; return; }
    idx -= TT * 4 * EH;
    if (idx < TT * 4 * EH) { g_xw1[idx] = bl1[idx % (4 * EH)]; return; }
    idx -= TT * 4 * EH;
    if (idx < DD * TH) { g_h2[idx] = b_t2[idx % TH]; return; }
}
#define FILL_ALL_N (TT * EH + 2 * TT * 4 * EH + DD * TH)

// kl_alpha: elementwise over (K,T,L)
__global__ void k_kl_alpha(const float* __restrict__ mu, const float* __restrict__ ls) {
    const int N = KK * TT * LL;
    int idx = blockIdx.x * 256 + threadIdx.x;
    float c = 0.0f;
    if (idx < N) {
        int r = idx % (TT * LL);
        int t = r / LL;
        float qm = mu[idx], ql = ls[idx];
        if (t == 0) {
            c = (expf(ql) + qm * qm) / (1.0f + 1e-6f) - 1.0f - ql;
        } else {
            const float LOGD = -5.2983174f;
            float den = expf(LOGD) + 1e-6f;
            float dm = qm - mu[idx - LL];
            c = (expf(ql) + dm * dm) / den - 1.0f + LOGD - ql;
        }
    }
    __shared__ float sr[8];
    float s = block_reduce_256(c, sr);
    if (threadIdx.x == 0) atomicAdd(&g_acc[1], 0.5 * (double)s);
}

// batched transpose of the 4 small weight matrices (z selects)
__global__ void k_transpose4(const float* __restrict__ A0, float* __restrict__ B0,
                             const float* __restrict__ A1, float* __restrict__ B1,
                             const float* __restrict__ A2, float* __restrict__ B2,
                             const float* __restrict__ A3, float* __restrict__ B3) {
    const float* A; float* B; int M, N;
    switch (blockIdx.z) {
        case 0:  A = A0; B = B0; M = EH + KK; N = KK; break;
        case 1:  A = A1; B = B1; M = EH + KK; N = KK; break;
        case 2:  A = A2; B = B2; M = TH;      N = KK; break;
        default: A = A3; B = B3; M = TH;      N = KK; break;
    }
    int m0 = blockIdx.x * 32, n0 = blockIdx.y * 32;
    if (m0 >= M || n0 >= N) return;
    __shared__ float tile[32][33];
    int tx = threadIdx.x, ty = threadIdx.y;
    int m = m0 + ty, n = n0 + tx;
    if (m < M && n < N) tile[ty][tx] = A[m * N + n];
    __syncthreads();
    int nb = n0 + ty, mb = m0 + tx;
    if (nb < N && mb < M) B[nb * M + mb] = tile[tx][ty];
}

__global__ void k_fill(float* __restrict__ C, const float* __restrict__ bias,
                       int M, int N) {
    int idx = blockIdx.x * 256 + threadIdx.x;
    if (idx < M * N) C[idx] = bias[idx % N];
}

// split-K tiled GEMM: C += A(MxK) @ B(KxN) over k-slice, atomic epilogue.
// reluA: apply relu to A elements on load.
__global__ void k_gemm_sk(const float* __restrict__ A, const float* __restrict__ B,
                          float* __restrict__ C, int M, int N, int Kd, int kchunk,
                          int reluA) {
    __shared__ float sA[16][65];
    __shared__ float sB[16][64];
    int tid = threadIdx.x;
    int tx = tid & 15, ty = tid >> 4;
    int row0 = blockIdx.y * 64 + ty * 4;
    int col0 = blockIdx.x * 64 + tx * 4;
    int kb = blockIdx.z * kchunk;
    int ke = min(kb + kchunk, Kd);
    float acc[4][4];
#pragma unroll
    for (int i = 0; i < 4; i++)
#pragma unroll
        for (int j = 0; j < 4; j++) acc[i][j] = 0.0f;

    for (int k0 = kb; k0 < ke; k0 += 16) {
#pragma unroll
        for (int i = 0; i < 4; i++) {
            int idx = tid + i * 256;
            int m = idx >> 4, kk = idx & 15;
            int gm = blockIdx.y * 64 + m, gk = k0 + kk;
            float v = 0.0f;
            if (gm < M && gk < ke) v = A[gm * Kd + gk];
            if (reluA) v = fmaxf(v, 0.0f);
            sA[kk][m] = v;
        }
#pragma unroll
        for (int i = 0; i < 4; i++) {
            int idx = tid + i * 256;
            int kk = idx >> 6, n = idx & 63;
            int gk = k0 + kk, gn = blockIdx.x * 64 + n;
            float v = 0.0f;
            if (gk < ke && gn < N) v = B[gk * N + gn];
            sB[kk][n] = v;
        }
        __syncthreads();
#pragma unroll
        for (int kk = 0; kk < 16; kk++) {
            float a[4], b[4];
#pragma unroll
            for (int i = 0; i < 4; i++) a[i] = sA[kk][ty * 4 + i];
#pragma unroll
            for (int j = 0; j < 4; j++) b[j] = sB[kk][tx * 4 + j];
#pragma unroll
            for (int i = 0; i < 4; i++)
#pragma unroll
                for (int j = 0; j < 4; j++) acc[i][j] += a[i] * b[j];
        }
        __syncthreads();
    }
#pragma unroll
    for (int i = 0; i < 4; i++)
#pragma unroll
        for (int j = 0; j < 4; j++) {
            int m = row0 + i, n = col0 + j;
            if (m < M && n < N) atomicAdd(&C[m * N + n], acc[i][j]);
        }
}

// ---------------- LSTM: cluster + DSMEM h-broadcast, reg weights ----------------
__global__ void __launch_bounds__(416) __cluster_dims__(4, 1, 1)
k_lstm_cluster(const float* __restrict__ xw, const float* __restrict__ Whh,
               float* __restrict__ hs) {
    __shared__ float s_xw[TT * 200];               // 40 KB
    __shared__ __align__(16) float h_s[EH];
    __shared__ float c_s[50];
    __shared__ float g_loc[200];
    const int b = blockIdx.x;
    const int tid = threadIdx.x;
    const int o = ((tid >> 1) % 200);
    const int half = tid & 1;
    const int gi = o / 50, e = o - gi * 50;
    const int col = gi * 200 + b * 50 + e;

    float w[100];
    if (tid < 400) {
#pragma unroll
        for (int j = 0; j < 100; j++)
            w[j] = Whh[(half * 100 + j) * 800 + col];
    }
    for (int idx = tid; idx < TT * 200; idx += 416) {
        int t = idx / 200, oo = idx - (idx / 200) * 200;
        int gg = oo / 50, ee = oo - gg * 50;
        s_xw[idx] = xw[t * 800 + gg * 200 + b * 50 + ee];
    }
    if (tid < EH) h_s[tid] = 0.0f;
    if (tid < 50) c_s[tid] = 0.0f;
    __syncthreads();
    asm volatile("barrier.cluster.arrive.aligned;" ::: "memory");
    asm volatile("barrier.cluster.wait.aligned;" ::: "memory");

    const unsigned h_addr = smem_u32(h_s);

    for (int t = 0; t < TT; t++) {
        float s = 0.0f;
        if (tid < 400) {
            const float4* hv = ((const float4*)h_s) + half * 25;
            float4 a = make_float4(0.f, 0.f, 0.f, 0.f);
#pragma unroll
            for (int j = 0; j < 25; j++) {
                float4 h4 = hv[j];
                a.x = fmaf(w[4 * j + 0], h4.x, a.x);
                a.y = fmaf(w[4 * j + 1], h4.y, a.y);
                a.z = fmaf(w[4 * j + 2], h4.z, a.z);
                a.w = fmaf(w[4 * j + 3], h4.w, a.w);
            }
            s = (a.x + a.y) + (a.z + a.w);
        }
        s += __shfl_down_sync(0xffffffffu, s, 1);
        if (half == 0 && tid < 400) g_loc[o] = s + s_xw[t * 200 + o];
        __syncthreads();
        if (tid < 50) {
            float ig = sigm(g_loc[tid]);
            float fg = sigm(g_loc[50 + tid]);
            float gg = tanhf(g_loc[100 + tid]);
            float og = sigm(g_loc[150 + tid]);
            float c = fg * c_s[tid] + ig * gg;
            float h = og * tanhf(c);
            c_s[tid] = c;
            __stcg(&hs[t * EH + b * 50 + tid], h);
            unsigned dst = h_addr + (unsigned)(b * 50 + tid) * 4u;
#pragma unroll
            for (int r = 0; r < 4; r++) dsmem_st(dst, r, h);
        }
        // arrive releases this thread's DSMEM writes; wait acquires peers'.
        asm volatile("barrier.cluster.arrive.aligned;" ::: "memory");
        asm volatile("barrier.cluster.wait.aligned;" ::: "memory");
    }
}

// eta pre: Amu/Als[t,k] = bias[k] + hs1[t,:] . W[:,k]  (coalesced via transposed W)
__global__ void __launch_bounds__(128) k_eta_pre(const float* __restrict__ hs1,
                                                 const float* __restrict__ bmu,
                                                 const float* __restrict__ bls) {
    int t = blockIdx.x;
    __shared__ float h[EH];
    int tid = threadIdx.x, warp = tid >> 5, lane = tid & 31;
    for (int i = tid; i < EH; i += 128) h[i] = hs1[t * EH + i];
    __syncthreads();
    for (int job = warp; job < 2 * KK; job += 4) {
        int k = job >> 1, isls = job & 1;
        const float* W = (isls ? g_WlseT : g_WmueT) + k * (EH + KK);
        float s = 0.0f;
#pragma unroll
        for (int i = lane; i < EH; i += 32) s += h[i] * W[i];
#pragma unroll
        for (int off = 16; off; off >>= 1) s += __shfl_down_sync(0xffffffffu, s, off);
        if (lane == 0) {
            s += isls ? bls[k] : bmu[k];
            (isls ? g_Als : g_Amu)[t * KK + k] = s;
        }
    }
}

// eta scan v2
__global__ void __launch_bounds__(128) k_eta2(const float* __restrict__ Amu,
                                              const float* __restrict__ Als) {
    __shared__ float eta_s[KK];
    __shared__ float mu_s[KK], ls_s[KK];
    __shared__ float kl_sh[2];
    int tid = threadIdx.x;
    int warp = tid >> 5;
    if (tid < KK) eta_s[tid] = 0.0f;
    __syncthreads();
    double kl_acc = 0.0;
    const float LOGD = -5.2983174f;
    for (int t = 0; t < TT; t++) {
        if (tid < KK) {
            float s = Amu[t * KK + tid];
            const float* W = &g_WmueT[tid * (EH + KK) + EH];
#pragma unroll
            for (int j = 0; j < KK; j++) s += eta_s[j] * W[j];
            mu_s[tid] = s;
        } else if (tid >= 64 && tid < 64 + KK) {
            int k = tid - 64;
            float s = Als[t * KK + k];
            const float* W = &g_WlseT[k * (EH + KK) + EH];
#pragma unroll
            for (int j = 0; j < KK; j++) s += eta_s[j] * W[j];
            ls_s[k] = s;
        }
        __syncthreads();
        if (tid < 64) {
            float term = 0.0f;
            if (tid < KK) {
                float pls = (t == 0) ? 0.0f : LOGD;
                float den = expf(pls) + 1e-6f;
                float dm = mu_s[tid] - eta_s[tid];
                term = (expf(ls_s[tid]) + dm * dm) / den - 1.0f + pls - ls_s[tid];
            }
#pragma unroll
            for (int off = 16; off; off >>= 1) term += __shfl_down_sync(0xffffffffu, term, off);
            if ((tid & 31) == 0) kl_sh[warp] = term;
        }
        __syncthreads();
        if (tid == 0) kl_acc += (double)(kl_sh[0] + kl_sh[1]);
        if (tid < KK) {
            eta_s[tid] = mu_s[tid];
            g_etas[t * KK + tid] = mu_s[tid];
        }
        __syncthreads();
    }
    if (tid == 0) g_acc[2] = 0.5 * kl_acc;
}

// eta_td scatter
__global__ void k_etatd(const int* __restrict__ times) {
    int idx = blockIdx.x * 256 + threadIdx.x;
    if (idx >= DD * KK) return;
    int d = idx / KK, k = idx - d * KK;
    g_eta_td[idx] = g_etas[times[d] * KK + k];
}

// mu_th / ls_th + softmax theta + kl_theta (relu applied on h2 load)
__global__ void __launch_bounds__(128) k_muls(const float* __restrict__ bmu,
                                              const float* __restrict__ bls) {
    int d = blockIdx.x;
    __shared__ float h_s[TH];
    __shared__ float mu_s[KK], ls_s[KK];
    int tid = threadIdx.x, warp = tid >> 5, lane = tid & 31;
    for (int i = tid; i < TH; i += 128) h_s[i] = fmaxf(g_h2[d * TH + i], 0.0f);
    __syncthreads();
    for (int job = warp; job < 2 * KK; job += 4) {
        int k = job >> 1, isls = job & 1;
        const float* W = isls ? g_WlsthT : g_WmuthT;
        float s = 0.0f;
        for (int i = lane; i < TH; i += 32) s += h_s[i] * W[k * TH + i];
#pragma unroll
        for (int off = 16; off; off >>= 1) s += __shfl_down_sync(0xffffffffu, s, off);
        if (lane == 0) {
            s += isls ? bls[k] : bmu[k];
            if (isls) ls_s[k] = s; else mu_s[k] = s;
        }
    }
    __syncthreads();
    if (tid == 0) {
        float m = -1e30f;
        for (int k = 0; k < KK; k++) m = fmaxf(m, mu_s[k]);
        float sum = 0.0f;
        for (int k = 0; k < KK; k++) sum += expf(mu_s[k] - m);
        float inv = 1.0f / sum;
        double kl = 0.0;
        for (int k = 0; k < KK; k++) {
            g_theta[d * KK + k] = expf(mu_s[k] - m) * inv;
            float mu = mu_s[k], ls = ls_s[k], eta = g_eta_td[d * KK + k];
            float dm = mu - eta;
            kl += (double)((expf(ls) + dm * dm) / (1.0f + 1e-6f) - 1.0f - ls);
        }
        atomicAdd(&g_acc[3], 0.5 * kl);
    }
}

// wa[d,k,l] = alpha[k, t_d, l] * lam[s_d, l]
__global__ void k_wa(const float* __restrict__ alpha, const float* __restrict__ lam,
                     const int* __restrict__ times, const int* __restrict__ sources) {
    int idx = blockIdx.x * 256 + threadIdx.x;
    if (idx >= DD * KK * LL) return;
    int d = idx / (KK * LL);
    int r = idx - d * (KK * LL);
    int k = r / LL;
    int l = r - k * LL;
    int t = times[d], s = sources[d];
    g_wa[idx] = alpha[(k * TT + t) * LL + l] * lam[s * LL + l];
}

// ---------------- tf32 tensor-core batched GEMM + exp + Z, d-pair per block ---
// Processes 2 documents per block against one shared rho tile (halves rho L2
// traffic). E stored as bf16.
#define GK 32
#define GST 36
__global__ void __launch_bounds__(256) k_g1_mma(const float* __restrict__ rho) {
    __shared__ unsigned wa_s[64 * GST];      //  9216 B (refilled per d)
    __shared__ unsigned rho_s[256 * GST];    // 36864 B
    __shared__ float zsh[2][64];
    const int d0 = blockIdx.y * 2;
    const int v0 = blockIdx.x * 256;
    const int tid = threadIdx.x;
    const int warp = tid >> 5, lane = tid & 31;
    const int g = lane >> 2, tg = lane & 3;
    const int mhalf = warp >> 2, nq = warp & 3;

    if (tid < 128) ((float*)zsh)[tid] = 0.0f;

    float c[2][2][8][4];
#pragma unroll
    for (int dd = 0; dd < 2; dd++)
#pragma unroll
        for (int mi = 0; mi < 2; mi++)
#pragma unroll
            for (int ni = 0; ni < 8; ni++)
#pragma unroll
                for (int j = 0; j < 4; j++) c[dd][mi][ni][j] = 0.0f;

    for (int chunk = 0; chunk < 10; chunk++) {
        const int l0 = chunk * GK;
        // fill rho tile (shared by both d's)
#pragma unroll
        for (int it = 0; it < 8; it++) {
            int i = tid + it * 256;
            int n = i >> 3, kk4 = (i & 7) * 4;
            int v = v0 + n;
            float4 val = make_float4(0.f, 0.f, 0.f, 0.f);
            if (v < VV && l0 + kk4 + 3 < LL)
                val = *(const float4*)(rho + v * LL + l0 + kk4);
            unsigned* rs = rho_s + n * GST + kk4;
            rs[0] = f2tf32(val.x); rs[1] = f2tf32(val.y);
            rs[2] = f2tf32(val.z); rs[3] = f2tf32(val.w);
        }
#pragma unroll
        for (int dd = 0; dd < 2; dd++) {
            const float* __restrict__ wa = g_wa + (size_t)(d0 + dd) * KK * LL;
            // fill wa tile for this d
#pragma unroll
            for (int it = 0; it < 2; it++) {
                int i = tid + it * 256;
                int m = i >> 3, kk4 = (i & 7) * 4;
                float4 v = make_float4(0.f, 0.f, 0.f, 0.f);
                if (m < KK && l0 + kk4 + 3 < LL)
                    v = *(const float4*)(wa + m * LL + l0 + kk4);
                unsigned* ws = wa_s + m * GST + kk4;
                ws[0] = f2tf32(v.x); ws[1] = f2tf32(v.y);
                ws[2] = f2tf32(v.z); ws[3] = f2tf32(v.w);
            }
            __syncthreads();
#pragma unroll
            for (int ks = 0; ks < 4; ks++) {
                const int k0 = ks * 8;
                unsigned a[2][4], b[8][2];
#pragma unroll
                for (int mi = 0; mi < 2; mi++) {
                    int rb = (mhalf * 2 + mi) * 16 + g;
                    a[mi][0] = wa_s[rb * GST + k0 + tg];
                    a[mi][1] = wa_s[(rb + 8) * GST + k0 + tg];
                    a[mi][2] = wa_s[rb * GST + k0 + tg + 4];
                    a[mi][3] = wa_s[(rb + 8) * GST + k0 + tg + 4];
                }
#pragma unroll
                for (int ni = 0; ni < 8; ni++) {
                    int nb = (nq * 8 + ni) * 8 + g;
                    b[ni][0] = rho_s[nb * GST + k0 + tg];
                    b[ni][1] = rho_s[nb * GST + k0 + tg + 4];
                }
#pragma unroll
                for (int mi = 0; mi < 2; mi++)
#pragma unroll
                    for (int ni = 0; ni < 8; ni++)
                        mma_tf32(c[dd][mi][ni], a[mi], b[ni]);
            }
            __syncthreads();
        }
    }

    // epilogue per d: exp, bf16 store, Z reduce
#pragma unroll
    for (int dd = 0; dd < 2; dd++) {
        __nv_bfloat16* Ebase = g_E + (size_t)(d0 + dd) * KK * VV;
        float zlo[2] = {0.f, 0.f}, zhi[2] = {0.f, 0.f};
#pragma unroll
        for (int mi = 0; mi < 2; mi++) {
            int row_lo = (mhalf * 2 + mi) * 16 + g;
            int row_hi = row_lo + 8;
#pragma unroll
            for (int ni = 0; ni < 8; ni++) {
                int v = v0 + (nq * 8 + ni) * 8 + tg * 2;
                bool vok = (v < VV);
                float e0 = vok ? __expf(c[dd][mi][ni][0]) : 0.0f;
                float e1 = vok ? __expf(c[dd][mi][ni][1]) : 0.0f;
                float e2 = vok ? __expf(c[dd][mi][ni][2]) : 0.0f;
                float e3 = vok ? __expf(c[dd][mi][ni][3]) : 0.0f;
                if (row_lo < KK) {
                    if (vok) *(__nv_bfloat162*)(Ebase + (size_t)row_lo * VV + v) =
                        __floats2bfloat162_rn(e0, e1);
                    zlo[mi] += e0 + e1;
                }
                if (row_hi < KK) {
                    if (vok) *(__nv_bfloat162*)(Ebase + (size_t)row_hi * VV + v) =
                        __floats2bfloat162_rn(e2, e3);
                    zhi[mi] += e2 + e3;
                }
            }
            zlo[mi] += __shfl_xor_sync(0xffffffffu, zlo[mi], 1);
            zlo[mi] += __shfl_xor_sync(0xffffffffu, zlo[mi], 2);
            zhi[mi] += __shfl_xor_sync(0xffffffffu, zhi[mi], 1);
            zhi[mi] += __shfl_xor_sync(0xffffffffu, zhi[mi], 2);
            if (tg == 0) {
                if (row_lo < KK) atomicAdd(&zsh[dd][row_lo], zlo[mi]);
                if (row_hi < KK) atomicAdd(&zsh[dd][row_hi], zhi[mi]);
            }
        }
    }
    __syncthreads();
    if (tid < KK) atomicAdd(&g_Z[d0 * KK + tid], zsh[0][tid]);
    else if (tid >= 128 && tid < 128 + KK)
        atomicAdd(&g_Z[(d0 + 1) * KK + tid - 128], zsh[1][tid - 128]);
}

// nll: lik[d,v] = sum_k (theta/Z) * E ;  acc -= log(lik+1e-6)*bows
__global__ void k_nll(const float* __restrict__ bows) {
    int d = blockIdx.y;
    int v = blockIdx.x * 256 + threadIdx.x;
    __shared__ float wk[KK];
    if (threadIdx.x < KK)
        wk[threadIdx.x] = g_theta[d * KK + threadIdx.x] / g_Z[d * KK + threadIdx.x];
    __syncthreads();
    float term = 0.0f;
    if (v < VV) {
        const __nv_bfloat16* E = g_E + (size_t)d * KK * VV + v;
        float lik = 0.0f;
#pragma unroll
        for (int k = 0; k < KK; k++) lik += wk[k] * __bfloat162float(E[k * VV]);
        term = __logf(lik + 1e-6f) * bows[d * VV + v];
    }
    __shared__ float sr[8];
    float s = block_reduce_256(term, sr);
    if (threadIdx.x == 0) atomicAdd(&g_acc[0], -(double)s);
}

__global__ void k_final(float* out) {
    int i = threadIdx.x;
    if (i < 4) out[i] = (float)g_acc[i];
}

// ---------------- static setup (outside measured window) ----------------
struct StreamRes {
    cudaStream_t sB;
    cudaEvent_t evFork, evJoin, evH1, evT;
    bool ok;
    StreamRes() {
        ok = true;
        int loPri = 0, hiPri = 0;
        cudaDeviceGetStreamPriorityRange(&loPri, &hiPri);
        if (cudaStreamCreateWithPriority(&sB, cudaStreamNonBlocking, loPri) != cudaSuccess)
            ok = false;
        if (ok && cudaEventCreateWithFlags(&evFork, cudaEventDisableTiming) != cudaSuccess) ok = false;
        if (ok && cudaEventCreateWithFlags(&evJoin, cudaEventDisableTiming) != cudaSuccess) ok = false;
        if (ok && cudaEventCreateWithFlags(&evH1, cudaEventDisableTiming) != cudaSuccess) ok = false;
        if (ok && cudaEventCreateWithFlags(&evT, cudaEventDisableTiming) != cudaSuccess) ok = false;
        if (ok) {
            k_warm<<<1, 1, 0, sB>>>();
            if (cudaStreamSynchronize(sB) != cudaSuccess) ok = false;
        }
        (void)cudaGetLastError();
    }
};
static StreamRes g_sr;

// ---------------- launch ----------------
extern "C" void kernel_launch(void* const* d_in, const int* in_sizes, int n_in,
                              void* d_out, int out_size) {
    const float* bows    = (const float*)d_in[0];
    const float* rnn_inp = (const float*)d_in[1];
    const int*   times   = (const int*)d_in[2];
    const int*   sources = (const int*)d_in[3];
    const float* rho     = (const float*)d_in[4];
    const float* lam     = (const float*)d_in[5];
    const float* mu_qa   = (const float*)d_in[6];
    const float* ls_qa   = (const float*)d_in[7];
    const float* W_t1    = (const float*)d_in[8];
    const float* b_t1    = (const float*)d_in[9];
    const float* W_t2    = (const float*)d_in[10];
    const float* b_t2    = (const float*)d_in[11];
    const float* W_mu_th = (const float*)d_in[12];
    const float* b_mu_th = (const float*)d_in[13];
    const float* W_ls_th = (const float*)d_in[14];
    const float* b_ls_th = (const float*)d_in[15];
    const float* W_em    = (const float*)d_in[16];
    const float* b_em    = (const float*)d_in[17];
    const float* Wih0    = (const float*)d_in[18];
    const float* Whh0    = (const float*)d_in[19];
    const float* bl0     = (const float*)d_in[20];
    const float* Wih1    = (const float*)d_in[21];
    const float* Whh1    = (const float*)d_in[22];
    const float* bl1     = (const float*)d_in[23];
    const float* W_mu_e  = (const float*)d_in[24];
    const float* b_mu_e  = (const float*)d_in[25];
    const float* W_ls_e  = (const float*)d_in[26];
    const float* b_ls_e  = (const float*)d_in[27];

    float *p_x, *p_xw0, *p_xw1, *p_hs0, *p_hs1, *p_h1, *p_h2;
    float *p_WmueT, *p_WlseT, *p_WmuthT, *p_WlsthT, *p_Amu, *p_Als, *p_etd;
    cudaGetSymbolAddress((void**)&p_x, g_x);
    cudaGetSymbolAddress((void**)&p_xw0, g_xw0);
    cudaGetSymbolAddress((void**)&p_xw1, g_xw1);
    cudaGetSymbolAddress((void**)&p_hs0, g_hs0);
    cudaGetSymbolAddress((void**)&p_hs1, g_hs1);
    cudaGetSymbolAddress((void**)&p_h1, g_h1);
    cudaGetSymbolAddress((void**)&p_h2, g_h2);
    cudaGetSymbolAddress((void**)&p_WmueT, g_WmueT);
    cudaGetSymbolAddress((void**)&p_WlseT, g_WlseT);
    cudaGetSymbolAddress((void**)&p_WmuthT, g_WmuthT);
    cudaGetSymbolAddress((void**)&p_WlsthT, g_WlsthT);
    cudaGetSymbolAddress((void**)&p_Amu, g_Amu);
    cudaGetSymbolAddress((void**)&p_Als, g_Als);
    cudaGetSymbolAddress((void**)&p_etd, g_eta_td);

    cudaStream_t sA = 0;
    cudaStream_t sB = g_sr.ok ? g_sr.sB : (cudaStream_t)0;

    // ---- common prologue ----
    k_zero<<<(DD * KK + 255) / 256, 256, 0, sA>>>();

    if (g_sr.ok) {
        cudaEventRecord(g_sr.evFork, sA);
        cudaStreamWaitEvent(sB, g_sr.evFork, 0);
    }

    // ---- chain B (low-priority stream) ----
    k_transpose4<<<dim3((TH + 31) / 32, (KK + 31) / 32, 4), dim3(32, 32), 0, sB>>>(
        W_mu_e, p_WmueT, W_ls_e, p_WlseT, W_mu_th, p_WmuthT, W_ls_th, p_WlsthT);
    if (g_sr.ok) cudaEventRecord(g_sr.evT, sB);
    k_kl_alpha<<<(KK * TT * LL + 255) / 256, 256, 0, sB>>>(mu_qa, ls_qa);
    k_wa<<<(DD * KK * LL + 255) / 256, 256, 0, sB>>>(mu_qa, lam, times, sources);
    k_fill<<<(DD * TH + 255) / 256, 256, 0, sB>>>(p_h1, b_t1, DD, TH);
    k_gemm_sk<<<dim3((TH + 63) / 64, (DD + 63) / 64, 6), 256, 0, sB>>>(bows, W_t1, p_h1, DD, TH, VV, (VV + 5) / 6, 0);
    if (g_sr.ok) cudaEventRecord(g_sr.evH1, sB);
    k_g1_mma<<<dim3(12, DD / 2), 256, 0, sB>>>(rho);
    if (g_sr.ok) cudaEventRecord(g_sr.evJoin, sB);

    // ---- chain A (default stream, higher priority): sequential path ----
    k_fill_all<<<(FILL_ALL_N + 255) / 256, 256, 0, sA>>>(b_em, bl0, bl1, b_t2);
    k_gemm_sk<<<dim3((EH + 63) / 64, 1, 12), 256, 0, sA>>>(rnn_inp, W_em, p_x, TT, EH, VV, (VV + 11) / 12, 0);

    k_gemm_sk<<<dim3((4 * EH + 63) / 64, 1, 4), 256, 0, sA>>>(p_x, Wih0, p_xw0, TT, 4 * EH, EH, EH / 4, 0);
    k_lstm_cluster<<<4, 416, 0, sA>>>(p_xw0, Whh0, p_hs0);

    k_gemm_sk<<<dim3((4 * EH + 63) / 64, 1, 4), 256, 0, sA>>>(p_hs0, Wih1, p_xw1, TT, 4 * EH, EH, EH / 4, 0);
    k_lstm_cluster<<<4, 416, 0, sA>>>(p_xw1, Whh1, p_hs1);

    // eta precompute (coalesced via transposed weights) + scan
    if (g_sr.ok) cudaStreamWaitEvent(sA, g_sr.evT, 0);
    k_eta_pre<<<TT, 128, 0, sA>>>(p_hs1, b_mu_e, b_ls_e);
    k_eta2<<<1, 128, 0, sA>>>(p_Amu, p_Als);
    k_etatd<<<(DD * KK + 255) / 256, 256, 0, sA>>>(times);

    // theta MLP: add eta part to h1; h2 = relu(h1)@W_t2 (relu fused on A-load);
    // muls applies relu on h2 load.
    if (g_sr.ok) cudaStreamWaitEvent(sA, g_sr.evH1, 0);
    k_gemm_sk<<<dim3((TH + 63) / 64, (DD + 63) / 64, 1), 256, 0, sA>>>(p_etd, W_t1 + VV * TH, p_h1, DD, TH, KK, KK, 0);
    k_gemm_sk<<<dim3((TH + 63) / 64, (DD + 63) / 64, 3), 256, 0, sA>>>(p_h1, W_t2, p_h2, DD, TH, TH, (TH + 2) / 3, 1);
    k_muls<<<DD, 128, 0, sA>>>(b_mu_th, b_ls_th);

    // ---- join, then nll + output ----
    if (g_sr.ok) cudaStreamWaitEvent(sA, g_sr.evJoin, 0);
    k_nll<<<dim3((VV + 255) / 256, DD), 256, 0, sA>>>(bows);
    k_final<<<1, 4, 0, sA>>>((float*)d_out);
    (void)in_sizes; (void)n_in; (void)out_size;
}